// round 1
// baseline (speedup 1.0000x reference)
#include <cuda_runtime.h>

// SplitMLP: y[b,g,o] = relu(day[b,:]·W1_day[g,h,:] + items[b,g,:]·W1_var[g,h,:] + b1[g,h]) · W2[g,o,h] + b2[g,o]
// Shapes: B=128, C=16, V=32, H=64, O=4, G=10000 (G derived at launch).

constexpr int B = 128;
constexpr int C = 16;
constexpr int V = 32;
constexpr int H = 64;
constexpr int O = 4;
constexpr int KTOT = C + V;          // 48
constexpr int DAY_PITCH = 20;        // pad 16 -> 20 floats: conflict-free LDS.128

typedef unsigned long long u64;

__device__ __forceinline__ u64 ffma2(u64 a, u64 b, u64 c) {
    u64 d;
    asm("fma.rn.f32x2 %0, %1, %2, %3;" : "=l"(d) : "l"(a), "l"(b), "l"(c));
    return d;
}
__device__ __forceinline__ u64 pack2(float lo, float hi) {
    u64 d;
    asm("mov.b64 %0, {%1, %2};" : "=l"(d) : "f"(lo), "f"(hi));
    return d;
}
__device__ __forceinline__ float2 unpack2(u64 a) {
    float lo, hi;
    asm("mov.b64 {%0, %1}, %2;" : "=f"(lo), "=f"(hi) : "l"(a));
    return make_float2(lo, hi);
}

__global__ __launch_bounds__(128) void splitmlp_kernel(
    const float* __restrict__ day,     // (B, C)
    const float* __restrict__ items,   // (B, G, V)
    const float* __restrict__ W1_day,  // (G, H, C)
    const float* __restrict__ W1_var,  // (G, H, V)
    const float* __restrict__ b1,      // (G, H)
    const float* __restrict__ W2,      // (G, O, H)
    const float* __restrict__ b2,      // (G, O)
    float* __restrict__ out,           // (B, G, O)
    int G)
{
    __shared__ float sW1[H][KTOT];          // [64][48]: k<16 day, k>=16 var
    __shared__ float sDay[B][DAY_PITCH];    // padded for conflict-free per-thread row reads
    __shared__ float sW2t[H][O];            // transposed: [hh][o]
    __shared__ float sB1[H];
    __shared__ float sB2[O];

    const int g = blockIdx.x;
    const int t = threadIdx.x;  // = batch row b

    // Kick off this thread's items row (128B contiguous) before staging sync.
    float4 it4[V / 4];
    const float4* itp = reinterpret_cast<const float4*>(items + ((size_t)t * G + g) * V);
#pragma unroll
    for (int i = 0; i < V / 4; ++i) it4[i] = itp[i];

    // --- cooperative staging (all coalesced) ---
    const float4* wd = reinterpret_cast<const float4*>(W1_day + (size_t)g * H * C);
#pragma unroll
    for (int j = 0; j < 2; ++j) {                 // 256 float4
        int f = t + j * 128;
        int hh = f >> 2, k4 = f & 3;
        *reinterpret_cast<float4*>(&sW1[hh][k4 * 4]) = wd[f];
    }
    const float4* wv = reinterpret_cast<const float4*>(W1_var + (size_t)g * H * V);
#pragma unroll
    for (int j = 0; j < 4; ++j) {                 // 512 float4
        int f = t + j * 128;
        int hh = f >> 3, k4 = f & 7;
        *reinterpret_cast<float4*>(&sW1[hh][C + k4 * 4]) = wv[f];
    }
    const float4* dp = reinterpret_cast<const float4*>(day);
#pragma unroll
    for (int j = 0; j < 4; ++j) {                 // 512 float4 (B*C/4)
        int f = t + j * 128;
        int bb = f >> 2, c4 = f & 3;
        *reinterpret_cast<float4*>(&sDay[bb][c4 * 4]) = dp[f];
    }
    const float* w2g = W2 + (size_t)g * O * H;
#pragma unroll
    for (int j = 0; j < 2; ++j) {                 // 256 scalars, transpose
        int f = t + j * 128;
        int o = f >> 6, hh = f & 63;
        sW2t[hh][o] = w2g[f];
    }
    if (t < H) sB1[t] = b1[(size_t)g * H + t];
    if (t < O) sB2[t] = b2[(size_t)g * O + t];
    __syncthreads();

    // --- per-thread x vector: 24 packed f32x2 pairs (day 0..15, items 16..47) ---
    u64 x2[KTOT / 2];
#pragma unroll
    for (int i = 0; i < 4; ++i) {
        float4 d4 = *reinterpret_cast<const float4*>(&sDay[t][i * 4]);
        x2[i * 2 + 0] = pack2(d4.x, d4.y);
        x2[i * 2 + 1] = pack2(d4.z, d4.w);
    }
#pragma unroll
    for (int i = 0; i < 8; ++i) {
        x2[8 + i * 2 + 0] = pack2(it4[i].x, it4[i].y);
        x2[8 + i * 2 + 1] = pack2(it4[i].z, it4[i].w);
    }

    u64 y01 = pack2(sB2[0], sB2[1]);
    u64 y23 = pack2(sB2[2], sB2[3]);

#pragma unroll 4
    for (int hh = 0; hh < H; ++hh) {
        u64 a0 = 0, a1 = 0;
#pragma unroll
        for (int k4 = 0; k4 < KTOT / 4; ++k4) {   // 12x LDS.128 broadcast
            ulonglong2 wp = *reinterpret_cast<const ulonglong2*>(&sW1[hh][k4 * 4]);
            a0 = ffma2(wp.x, x2[2 * k4 + 0], a0);
            a1 = ffma2(wp.y, x2[2 * k4 + 1], a1);
        }
        float2 s0 = unpack2(a0), s1 = unpack2(a1);
        float acc = sB1[hh] + ((s0.x + s0.y) + (s1.x + s1.y));
        acc = fmaxf(acc, 0.0f);
        u64 ap = pack2(acc, acc);
        ulonglong2 wo = *reinterpret_cast<const ulonglong2*>(&sW2t[hh][0]);
        y01 = ffma2(wo.x, ap, y01);
        y23 = ffma2(wo.y, ap, y23);
    }

    float2 r01 = unpack2(y01), r23 = unpack2(y23);
    float4 res = make_float4(r01.x, r01.y, r23.x, r23.y);
    *reinterpret_cast<float4*>(out + ((size_t)t * G + g) * O) = res;
}

extern "C" void kernel_launch(void* const* d_in, const int* in_sizes, int n_in,
                              void* d_out, int out_size) {
    const float* day    = (const float*)d_in[0];
    const float* items  = (const float*)d_in[1];
    const float* W1_day = (const float*)d_in[2];
    const float* W1_var = (const float*)d_in[3];
    const float* b1     = (const float*)d_in[4];
    const float* W2     = (const float*)d_in[5];
    const float* b2     = (const float*)d_in[6];
    float* out = (float*)d_out;

    const int G = in_sizes[1] / (B * V);   // items = B*G*V

    splitmlp_kernel<<<G, 128>>>(day, items, W1_day, W1_var, b1, W2, b2, out, G);
}

// round 5
// speedup vs baseline: 2.5679x; 2.5679x over previous
#include <cuda_runtime.h>
#include <cuda_bf16.h>
#include <cstdint>

// SplitMLP via mma.sync bf16 (hi/lo split, 3 cross-products ~ fp32 accuracy):
//   h = relu(X(128x48) @ W1^T(48x64) + b1);  y = h @ W2^T(64x4) + b2
// X = [day | items_g]. fc1 on legacy-path tensor cores (HMMA.16816.BF16),
// fc2 + ReLU in-register epilogue with quad shuffle reduction.

constexpr int B = 128;
constexpr int C = 16;
constexpr int V = 32;
constexpr int H = 64;
constexpr int O = 4;
constexpr int KTOT = 48;
constexpr int PX = 104;              // bf16 pitch: 48 hi + 48 lo + 8 pad (208 B)
constexpr int PXB = PX * 2;          // 208 bytes; 8 rows cover all 32 banks

typedef uint32_t u32;

// ---------- helpers ----------
__device__ __forceinline__ u32 smem_u32(const void* p) {
    u32 a;
    asm("{ .reg .u64 t; cvta.to.shared.u64 t, %1; cvt.u32.u64 %0, t; }"
        : "=r"(a) : "l"(p));
    return a;
}
// pack two floats into bf16x2 (first arg -> low half)
__device__ __forceinline__ u32 cvt2bf16(float lo, float hi) {
    u32 d;
    asm("cvt.rn.bf16x2.f32 %0, %1, %2;" : "=r"(d) : "f"(hi), "f"(lo));
    return d;
}
__device__ __forceinline__ void ldsm4(u32* r, u32 addr) {
    asm volatile("ldmatrix.sync.aligned.m8n8.x4.shared.b16 {%0,%1,%2,%3}, [%4];"
                 : "=r"(r[0]), "=r"(r[1]), "=r"(r[2]), "=r"(r[3]) : "r"(addr));
}
__device__ __forceinline__ void mma_bf16(float* c, const u32* a, const u32* b) {
    asm volatile(
        "mma.sync.aligned.m16n8k16.row.col.f32.bf16.bf16.f32 "
        "{%0,%1,%2,%3}, {%4,%5,%6,%7}, {%8,%9}, {%0,%1,%2,%3};"
        : "+f"(c[0]), "+f"(c[1]), "+f"(c[2]), "+f"(c[3])
        : "r"(a[0]), "r"(a[1]), "r"(a[2]), "r"(a[3]), "r"(b[0]), "r"(b[1]));
}

// Convert float4 -> bf16 hi/lo pairs and store at (row, col) + (row, col+48).
__device__ __forceinline__ void cvt_store4(__nv_bfloat16* base, int row, int col,
                                           float4 v) {
    u32 h01 = cvt2bf16(v.x, v.y);
    u32 h23 = cvt2bf16(v.z, v.w);
    float l0 = v.x - __uint_as_float(h01 << 16);
    float l1 = v.y - __uint_as_float(h01 & 0xffff0000u);
    float l2 = v.z - __uint_as_float(h23 << 16);
    float l3 = v.w - __uint_as_float(h23 & 0xffff0000u);
    u32 lo01 = cvt2bf16(l0, l1);
    u32 lo23 = cvt2bf16(l2, l3);
    *reinterpret_cast<uint2*>(base + row * PX + col) = make_uint2(h01, h23);
    *reinterpret_cast<uint2*>(base + row * PX + col + KTOT) = make_uint2(lo01, lo23);
}

__global__ __launch_bounds__(128) void splitmlp_mma(
    const float* __restrict__ day,     // (B, C)
    const float* __restrict__ items,   // (B, G, V)
    const float* __restrict__ W1_day,  // (G, H, C)
    const float* __restrict__ W1_var,  // (G, H, V)
    const float* __restrict__ b1,      // (G, H)
    const float* __restrict__ W2,      // (G, O, H)
    const float* __restrict__ b2,      // (G, O)
    float* __restrict__ out,           // (B, G, O)
    int G)
{
    __shared__ __nv_bfloat16 sX[B * PX];    // 26624 B
    __shared__ __nv_bfloat16 sW1[H * PX];   // 13312 B
    __shared__ float sW2[O * H];            // [o][h]
    __shared__ float sB1[H];
    __shared__ float sB2[O];

    const int t = threadIdx.x;
    const int wid = t >> 5;
    const int lane = t & 31;
    const int g = blockIdx.x;

    // ---- stage + convert (all coalesced float4 global loads) ----
    {   // day: 512 float4 -> X rows, k 0..15
        const float4* p = reinterpret_cast<const float4*>(day);
#pragma unroll
        for (int j = 0; j < 4; ++j) {
            int f = t + j * 128;
            cvt_store4(sX, f >> 2, (f & 3) * 4, p[f]);
        }
    }
    {   // items: 1024 float4 -> X rows, k 16..47
        const float4* p = reinterpret_cast<const float4*>(items);
#pragma unroll
        for (int j = 0; j < 8; ++j) {
            int f = t + j * 128;
            int bb = f >> 3;
            float4 v = p[((size_t)bb * G + g) * (V / 4) + (f & 7)];
            cvt_store4(sX, bb, 16 + (f & 7) * 4, v);
        }
    }
    {   // W1_day: 256 float4 -> W1 rows, k 0..15
        const float4* p = reinterpret_cast<const float4*>(W1_day) + (size_t)g * (H * C / 4);
#pragma unroll
        for (int j = 0; j < 2; ++j) {
            int f = t + j * 128;
            cvt_store4(sW1, f >> 2, (f & 3) * 4, p[f]);
        }
    }
    {   // W1_var: 512 float4 -> W1 rows, k 16..47
        const float4* p = reinterpret_cast<const float4*>(W1_var) + (size_t)g * (H * V / 4);
#pragma unroll
        for (int j = 0; j < 4; ++j) {
            int f = t + j * 128;
            cvt_store4(sW1, f >> 3, 16 + (f & 7) * 4, p[f]);
        }
    }
    if (t < 64) {
        reinterpret_cast<float4*>(sW2)[t] =
            reinterpret_cast<const float4*>(W2)[(size_t)g * (O * H / 4) + t];
    }
    if (t < 16) {
        reinterpret_cast<float4*>(sB1)[t] =
            reinterpret_cast<const float4*>(b1)[(size_t)g * (H / 4) + t];
    }
    if (t == 0) {
        *reinterpret_cast<float4*>(sB2) = reinterpret_cast<const float4*>(b2)[g];
    }
    __syncthreads();

    // ---- per-lane ldmatrix addresses ----
    const u32 sbX = smem_u32(sX);
    const u32 sbW = smem_u32(sW1);
    const int r8 = lane & 7, sel = lane >> 3;
    const int wbase = wid * 32;
    // A: m0=rows0-7 klo, m1=rows8-15 klo, m2=rows0-7 khi, m3=rows8-15 khi
    const u32 aAddr = sbX + (u32)((wbase + ((sel & 1) << 3) + r8) * PXB +
                                  ((sel & 2) ? 16 : 0));
    // B: m0=n0-7 klo, m1=n0-7 khi, m2=n8-15 klo, m3=n8-15 khi
    const u32 bAddr = sbW + (u32)(((((sel >> 1) & 1) << 3) + r8) * PXB +
                                  ((sel & 1) << 4));
    constexpr int MT_STRIDE = 16 * PXB;     // A m-tile stride
    constexpr int NT_STRIDE = 16 * PXB;     // B 16-row group stride
    constexpr int LO_OFF = KTOT * 2;        // 96 bytes to lo plane

    float acc[2][8][4];
#pragma unroll
    for (int mt = 0; mt < 2; ++mt)
#pragma unroll
        for (int nt = 0; nt < 8; ++nt)
#pragma unroll
            for (int i = 0; i < 4; ++i) acc[mt][nt][i] = 0.0f;

#pragma unroll
    for (int kk = 0; kk < 3; ++kk) {
        const int kOff = kk * 32;           // 16 bf16 = 32 B per k-chunk
        u32 ah[2][4], bh[4][4];
#pragma unroll
        for (int mt = 0; mt < 2; ++mt)
            ldsm4(ah[mt], aAddr + mt * MT_STRIDE + kOff);
#pragma unroll
        for (int np = 0; np < 4; ++np)
            ldsm4(bh[np], bAddr + np * NT_STRIDE + kOff);
        // pass 1: Ah * Bh
#pragma unroll
        for (int mt = 0; mt < 2; ++mt)
#pragma unroll
            for (int np = 0; np < 4; ++np) {
                mma_bf16(acc[mt][2 * np + 0], ah[mt], &bh[np][0]);
                mma_bf16(acc[mt][2 * np + 1], ah[mt], &bh[np][2]);
            }
        // pass 2: Ah * Bl
#pragma unroll
        for (int np = 0; np < 4; ++np) {
            u32 bl[4];
            ldsm4(bl, bAddr + np * NT_STRIDE + LO_OFF + kOff);
#pragma unroll
            for (int mt = 0; mt < 2; ++mt) {
                mma_bf16(acc[mt][2 * np + 0], ah[mt], &bl[0]);
                mma_bf16(acc[mt][2 * np + 1], ah[mt], &bl[2]);
            }
        }
        // pass 3: Al * Bh
#pragma unroll
        for (int mt = 0; mt < 2; ++mt) {
            u32 al[4];
            ldsm4(al, aAddr + mt * MT_STRIDE + LO_OFF + kOff);
#pragma unroll
            for (int np = 0; np < 4; ++np) {
                mma_bf16(acc[mt][2 * np + 0], al, &bh[np][0]);
                mma_bf16(acc[mt][2 * np + 1], al, &bh[np][2]);
            }
        }
    }

    // ---- epilogue: relu(h + b1), fc2, quad reduction ----
    // D-frag: c0,c1 = (row lane/4, h0/h1), c2,c3 = (row lane/4+8, h0/h1)
    // with h0 = nt*8 + (lane%4)*2, h1 = h0+1.
    float y[2][2][4];   // [mt][rowpos][o]
#pragma unroll
    for (int mt = 0; mt < 2; ++mt)
#pragma unroll
        for (int rp = 0; rp < 2; ++rp)
#pragma unroll
            for (int o = 0; o < O; ++o) y[mt][rp][o] = 0.0f;

    const int q = lane & 3;
#pragma unroll
    for (int nt = 0; nt < 8; ++nt) {
        const int h0 = nt * 8 + q * 2;
        const float2 bb = *reinterpret_cast<const float2*>(&sB1[h0]);
#pragma unroll
        for (int mt = 0; mt < 2; ++mt) {
            float v00 = fmaxf(acc[mt][nt][0] + bb.x, 0.0f);
            float v01 = fmaxf(acc[mt][nt][1] + bb.y, 0.0f);
            float v10 = fmaxf(acc[mt][nt][2] + bb.x, 0.0f);
            float v11 = fmaxf(acc[mt][nt][3] + bb.y, 0.0f);
#pragma unroll
            for (int o = 0; o < O; ++o) {
                const float2 w = *reinterpret_cast<const float2*>(&sW2[o * H + h0]);
                y[mt][0][o] = fmaf(v00, w.x, fmaf(v01, w.y, y[mt][0][o]));
                y[mt][1][o] = fmaf(v10, w.x, fmaf(v11, w.y, y[mt][1][o]));
            }
        }
    }
    // reduce across the quad (lanes sharing lane/4)
#pragma unroll
    for (int d = 1; d < 4; d <<= 1) {
#pragma unroll
        for (int mt = 0; mt < 2; ++mt)
#pragma unroll
            for (int rp = 0; rp < 2; ++rp)
#pragma unroll
                for (int o = 0; o < O; ++o)
                    y[mt][rp][o] += __shfl_xor_sync(0xffffffffu, y[mt][rp][o], d);
    }

    if (q == 0) {
        const int rbase = wbase + (lane >> 2);
#pragma unroll
        for (int mt = 0; mt < 2; ++mt)
#pragma unroll
            for (int rp = 0; rp < 2; ++rp) {
                const int row = rbase + mt * 16 + rp * 8;
                float4 res = make_float4(y[mt][rp][0] + sB2[0],
                                         y[mt][rp][1] + sB2[1],
                                         y[mt][rp][2] + sB2[2],
                                         y[mt][rp][3] + sB2[3]);
                *reinterpret_cast<float4*>(out + ((size_t)row * G + g) * O) = res;
            }
    }
}

extern "C" void kernel_launch(void* const* d_in, const int* in_sizes, int n_in,
                              void* d_out, int out_size) {
    const float* day    = (const float*)d_in[0];
    const float* items  = (const float*)d_in[1];
    const float* W1_day = (const float*)d_in[2];
    const float* W1_var = (const float*)d_in[3];
    const float* b1     = (const float*)d_in[4];
    const float* W2     = (const float*)d_in[5];
    const float* b2     = (const float*)d_in[6];
    float* out = (float*)d_out;

    const int G = in_sizes[1] / (B * V);   // items = B*G*V

    splitmlp_mma<<<G, 128>>>(day, items, W1_day, W1_var, b1, W2, b2, out, G);
}

// round 8
// speedup vs baseline: 2.8791x; 1.1212x over previous
#include <cuda_runtime.h>
#include <cuda_bf16.h>
#include <cstdint>

// SplitMLP via mma.sync bf16 (hi/lo split, 3 cross-products ~ fp32 accuracy).
// Multi-group CTAs (NG groups each) with register prefetch of group g+1's
// inputs overlapping group g's MMA — hides DRAM latency inside the CTA.

constexpr int B = 128;
constexpr int C = 16;
constexpr int V = 32;
constexpr int H = 64;
constexpr int O = 4;
constexpr int KTOT = 48;
constexpr int PX = 104;              // bf16 pitch: 48 hi + 48 lo + 8 pad (208 B)
constexpr int PXB = PX * 2;          // 208 bytes; 8 rows cover all 32 banks
constexpr int NG = 5;                // groups per CTA

typedef uint32_t u32;

// ---------- helpers ----------
__device__ __forceinline__ u32 smem_u32(const void* p) {
    u32 a;
    asm("{ .reg .u64 t; cvta.to.shared.u64 t, %1; cvt.u32.u64 %0, t; }"
        : "=r"(a) : "l"(p));
    return a;
}
__device__ __forceinline__ u32 cvt2bf16(float lo, float hi) {
    u32 d;
    asm("cvt.rn.bf16x2.f32 %0, %1, %2;" : "=r"(d) : "f"(hi), "f"(lo));
    return d;
}
__device__ __forceinline__ void ldsm4(u32* r, u32 addr) {
    asm volatile("ldmatrix.sync.aligned.m8n8.x4.shared.b16 {%0,%1,%2,%3}, [%4];"
                 : "=r"(r[0]), "=r"(r[1]), "=r"(r[2]), "=r"(r[3]) : "r"(addr));
}
__device__ __forceinline__ void mma_bf16(float* c, const u32* a, const u32* b) {
    asm volatile(
        "mma.sync.aligned.m16n8k16.row.col.f32.bf16.bf16.f32 "
        "{%0,%1,%2,%3}, {%4,%5,%6,%7}, {%8,%9}, {%0,%1,%2,%3};"
        : "+f"(c[0]), "+f"(c[1]), "+f"(c[2]), "+f"(c[3])
        : "r"(a[0]), "r"(a[1]), "r"(a[2]), "r"(a[3]), "r"(b[0]), "r"(b[1]));
}

// Convert float4 -> bf16 hi/lo pairs and store at (row, col) + (row, col+48).
__device__ __forceinline__ void cvt_store4(__nv_bfloat16* base, int row, int col,
                                           float4 v) {
    u32 h01 = cvt2bf16(v.x, v.y);
    u32 h23 = cvt2bf16(v.z, v.w);
    float l0 = v.x - __uint_as_float(h01 << 16);
    float l1 = v.y - __uint_as_float(h01 & 0xffff0000u);
    float l2 = v.z - __uint_as_float(h23 << 16);
    float l3 = v.w - __uint_as_float(h23 & 0xffff0000u);
    u32 lo01 = cvt2bf16(l0, l1);
    u32 lo23 = cvt2bf16(l2, l3);
    *reinterpret_cast<uint2*>(base + row * PX + col) = make_uint2(h01, h23);
    *reinterpret_cast<uint2*>(base + row * PX + col + KTOT) = make_uint2(lo01, lo23);
}

struct GroupRegs {
    float4 it[8];   // items slice
    float4 wd[2];   // W1_day
    float4 wv[4];   // W1_var
    float2 w2;      // W2 (128 float2 across 128 threads)
    float  b1v;     // t<64
    float  b2v;     // t<4
};

__device__ __forceinline__ void load_group(
    GroupRegs& r, int g, int t, int G,
    const float4* itBase, size_t itStrideJ,
    const float4* wdF4, const float4* wvF4,
    const float2* w2F2, const float* b1p, const float* b2p)
{
#pragma unroll
    for (int j = 0; j < 8; ++j) r.it[j] = itBase[(size_t)g * 8 + j * itStrideJ];
#pragma unroll
    for (int j = 0; j < 2; ++j) r.wd[j] = wdF4[(size_t)g * 256 + t + j * 128];
#pragma unroll
    for (int j = 0; j < 4; ++j) r.wv[j] = wvF4[(size_t)g * 512 + t + j * 128];
    r.w2 = w2F2[(size_t)g * 128 + t];
    if (t < 64) r.b1v = b1p[(size_t)g * 64 + t];
    if (t < 4)  r.b2v = b2p[(size_t)g * 4 + t];
}

__global__ __launch_bounds__(128, 2) void splitmlp_mma(
    const float* __restrict__ day,     // (B, C)
    const float* __restrict__ items,   // (B, G, V)
    const float* __restrict__ W1_day,  // (G, H, C)
    const float* __restrict__ W1_var,  // (G, H, V)
    const float* __restrict__ b1,      // (G, H)
    const float* __restrict__ W2,      // (G, O, H)
    const float* __restrict__ b2,      // (G, O)
    float* __restrict__ out,           // (B, G, O)
    int G)
{
    __shared__ __nv_bfloat16 sX[B * PX];    // 26624 B
    __shared__ __nv_bfloat16 sW1[H * PX];   // 13312 B
    __shared__ float sW2[O * H];            // [o][h]
    __shared__ float sB1[H];
    __shared__ float sB2[O];

    const int t = threadIdx.x;
    const int wid = t >> 5;
    const int lane = t & 31;
    const int g0 = blockIdx.x * NG;
    const int gEnd = (g0 + NG < G) ? (g0 + NG) : G;
    if (g0 >= G) return;

    // per-thread global bases
    const float4* itBase = reinterpret_cast<const float4*>(items) +
                           (size_t)(t >> 3) * G * 8 + (t & 7);
    const size_t itStrideJ = (size_t)128 * G;
    const float4* wdF4 = reinterpret_cast<const float4*>(W1_day);
    const float4* wvF4 = reinterpret_cast<const float4*>(W1_var);
    const float2* w2F2 = reinterpret_cast<const float2*>(W2);

    GroupRegs cur;
    load_group(cur, g0, t, G, itBase, itStrideJ, wdF4, wvF4, w2F2, b1, b2);

    // day staged once per CTA: X rows, k 0..15 (+lo plane)
    {
        const float4* p = reinterpret_cast<const float4*>(day);
#pragma unroll
        for (int j = 0; j < 4; ++j) {
            int f = t + j * 128;
            cvt_store4(sX, f >> 2, (f & 3) * 4, p[f]);
        }
    }

    // ---- per-lane ldmatrix addresses (group-invariant) ----
    const u32 sbX = smem_u32(sX);
    const u32 sbW = smem_u32(sW1);
    const int r8 = lane & 7, sel = lane >> 3;
    const int wbase = wid * 32;
    const u32 aAddr = sbX + (u32)((wbase + ((sel & 1) << 3) + r8) * PXB +
                                  ((sel & 2) ? 16 : 0));
    const u32 bAddr = sbW + (u32)(((((sel >> 1) & 1) << 3) + r8) * PXB +
                                  ((sel & 1) << 4));
    constexpr int MT_STRIDE = 16 * PXB;
    constexpr int NT_STRIDE = 16 * PXB;
    constexpr int LO_OFF = KTOT * 2;
    const int q = lane & 3;

#pragma unroll 1
    for (int g = g0; g < gEnd; ++g) {
        // ---- stage current group from registers ----
#pragma unroll
        for (int j = 0; j < 8; ++j)
            cvt_store4(sX, (t >> 3) + j * 16, 16 + (t & 7) * 4, cur.it[j]);
#pragma unroll
        for (int j = 0; j < 2; ++j)
            cvt_store4(sW1, (t >> 2) + j * 32, (t & 3) * 4, cur.wd[j]);
#pragma unroll
        for (int j = 0; j < 4; ++j)
            cvt_store4(sW1, (t >> 3) + j * 16, 16 + (t & 7) * 4, cur.wv[j]);
        reinterpret_cast<float2*>(sW2)[t] = cur.w2;
        if (t < 64) sB1[t] = cur.b1v;
        if (t < 4)  sB2[t] = cur.b2v;
        __syncthreads();

        // ---- prefetch next group (overlaps with MMA below) ----
        GroupRegs nxt;
        const bool more = (g + 1 < gEnd);
        if (more)
            load_group(nxt, g + 1, t, G, itBase, itStrideJ, wdF4, wvF4, w2F2, b1, b2);

        // ---- fc1 MMA: 3 k-chunks x 3 hi/lo passes ----
        float acc[2][8][4];
#pragma unroll
        for (int mt = 0; mt < 2; ++mt)
#pragma unroll
            for (int nt = 0; nt < 8; ++nt)
#pragma unroll
                for (int i = 0; i < 4; ++i) acc[mt][nt][i] = 0.0f;

#pragma unroll
        for (int kk = 0; kk < 3; ++kk) {
            const int kOff = kk * 32;
            u32 ah[2][4], bh[4][4];
#pragma unroll
            for (int mt = 0; mt < 2; ++mt)
                ldsm4(ah[mt], aAddr + mt * MT_STRIDE + kOff);
#pragma unroll
            for (int np = 0; np < 4; ++np)
                ldsm4(bh[np], bAddr + np * NT_STRIDE + kOff);
            // Ah * Bh
#pragma unroll
            for (int mt = 0; mt < 2; ++mt)
#pragma unroll
                for (int np = 0; np < 4; ++np) {
                    mma_bf16(acc[mt][2 * np + 0], ah[mt], &bh[np][0]);
                    mma_bf16(acc[mt][2 * np + 1], ah[mt], &bh[np][2]);
                }
            // Ah * Bl
#pragma unroll
            for (int np = 0; np < 4; ++np) {
                u32 bl[4];
                ldsm4(bl, bAddr + np * NT_STRIDE + LO_OFF + kOff);
#pragma unroll
                for (int mt = 0; mt < 2; ++mt) {
                    mma_bf16(acc[mt][2 * np + 0], ah[mt], &bl[0]);
                    mma_bf16(acc[mt][2 * np + 1], ah[mt], &bl[2]);
                }
            }
            // Al * Bh
#pragma unroll
            for (int mt = 0; mt < 2; ++mt) {
                u32 al[4];
                ldsm4(al, aAddr + mt * MT_STRIDE + LO_OFF + kOff);
#pragma unroll
                for (int np = 0; np < 4; ++np) {
                    mma_bf16(acc[mt][2 * np + 0], al, &bh[np][0]);
                    mma_bf16(acc[mt][2 * np + 1], al, &bh[np][2]);
                }
            }
        }

        // ---- epilogue: relu(h + b1), fc2, quad reduction ----
        float y[2][2][4];
#pragma unroll
        for (int mt = 0; mt < 2; ++mt)
#pragma unroll
            for (int rp = 0; rp < 2; ++rp)
#pragma unroll
                for (int o = 0; o < O; ++o) y[mt][rp][o] = 0.0f;

#pragma unroll
        for (int nt = 0; nt < 8; ++nt) {
            const int h0 = nt * 8 + q * 2;
            const float2 bb = *reinterpret_cast<const float2*>(&sB1[h0]);
#pragma unroll
            for (int mt = 0; mt < 2; ++mt) {
                float v00 = fmaxf(acc[mt][nt][0] + bb.x, 0.0f);
                float v01 = fmaxf(acc[mt][nt][1] + bb.y, 0.0f);
                float v10 = fmaxf(acc[mt][nt][2] + bb.x, 0.0f);
                float v11 = fmaxf(acc[mt][nt][3] + bb.y, 0.0f);
#pragma unroll
                for (int o = 0; o < O; ++o) {
                    const float2 w = *reinterpret_cast<const float2*>(&sW2[o * H + h0]);
                    y[mt][0][o] = fmaf(v00, w.x, fmaf(v01, w.y, y[mt][0][o]));
                    y[mt][1][o] = fmaf(v10, w.x, fmaf(v11, w.y, y[mt][1][o]));
                }
            }
        }
#pragma unroll
        for (int d = 1; d < 4; d <<= 1) {
#pragma unroll
            for (int mt = 0; mt < 2; ++mt)
#pragma unroll
                for (int rp = 0; rp < 2; ++rp)
#pragma unroll
                    for (int o = 0; o < O; ++o)
                        y[mt][rp][o] += __shfl_xor_sync(0xffffffffu, y[mt][rp][o], d);
        }

        if (q == 0) {
            const int rbase = wbase + (lane >> 2);
#pragma unroll
            for (int mt = 0; mt < 2; ++mt)
#pragma unroll
                for (int rp = 0; rp < 2; ++rp) {
                    const int row = rbase + mt * 16 + rp * 8;
                    float4 res = make_float4(y[mt][rp][0] + sB2[0],
                                             y[mt][rp][1] + sB2[1],
                                             y[mt][rp][2] + sB2[2],
                                             y[mt][rp][3] + sB2[3]);
                    *reinterpret_cast<float4*>(out + ((size_t)row * G + g) * O) = res;
                }
        }

        __syncthreads();   // smem reusable for next group's staging
        if (more) cur = nxt;
    }
}

extern "C" void kernel_launch(void* const* d_in, const int* in_sizes, int n_in,
                              void* d_out, int out_size) {
    const float* day    = (const float*)d_in[0];
    const float* items  = (const float*)d_in[1];
    const float* W1_day = (const float*)d_in[2];
    const float* W1_var = (const float*)d_in[3];
    const float* b1     = (const float*)d_in[4];
    const float* W2     = (const float*)d_in[5];
    const float* b2     = (const float*)d_in[6];
    float* out = (float*)d_out;

    const int G = in_sizes[1] / (B * V);   // items = B*G*V
    const int grid = (G + NG - 1) / NG;

    splitmlp_mma<<<grid, 128>>>(day, items, W1_day, W1_var, b1, W2, b2, out, G);
}